// round 1
// baseline (speedup 1.0000x reference)
#include <cuda_runtime.h>

// Problem constants (fixed by the dataset)
#define BB 32
#define NN 200
#define DD 100
#define IT 8              // i-rows per block (one warp per row)
#define JT 7              // ceil(N/32) j-slots per lane
#define CC (DD/4)         // 25 float4 chunks per row
#define HS_STRIDE 108     // padded row stride in floats: (12*lane)%32 -> conflict-free LDS.128
#define NPAD 224          // padded row count so j = lane + 32t is always in-bounds
#define NEGV (-9e15f)

#define SMEM_BYTES (NPAD*HS_STRIDE*4 + IT*4*DD*4)

__global__ __launch_bounds__(256, 2)
void gnn_agg_kernel(const int* __restrict__ inputs,
                    const int* __restrict__ adj,
                    const float* __restrict__ emb,
                    const float* __restrict__ a0,
                    const float* __restrict__ a1,
                    const float* __restrict__ a2,
                    const float* __restrict__ a3,
                    float* __restrict__ out)
{
    extern __shared__ float sm[];
    float* hs = sm;                          // [NPAD][HS_STRIDE]
    float* gg = sm + NPAD * HS_STRIDE;       // [IT][4][DD]
    __shared__ int ids[NN];

    const int b    = blockIdx.y;
    const int i0   = blockIdx.x * IT;
    const int tid  = threadIdx.x;
    const int w    = tid >> 5;
    const int lane = tid & 31;

    // ---- load item ids for this batch ----
    if (tid < NN) ids[tid] = inputs[b * NN + tid];
    __syncthreads();

    // ---- gather h[b] into shared (swizzle-free padded layout) ----
    for (int u = tid; u < NN * CC; u += 256) {
        int j = u / CC, c = u - j * CC;
        float4 v = *(const float4*)(emb + (size_t)ids[j] * DD + 4 * c);
        *(float4*)(hs + j * HS_STRIDE + 4 * c) = v;
    }
    // zero pad rows [NN, NPAD)
    for (int u = tid; u < (NPAD - NN) * CC; u += 256) {
        int j = NN + u / CC, c = u - (u / CC) * CC;
        *(float4*)(hs + j * HS_STRIDE + 4 * c) = make_float4(0.f, 0.f, 0.f, 0.f);
    }
    __syncthreads();

    const int i = i0 + w;

    // ---- g_k[d] = h[i][d] * a_k[d] (per-warp, broadcast-read later) ----
    float* gw = gg + w * 4 * DD;
    for (int d = lane; d < DD; d += 32) {
        float hv = hs[i * HS_STRIDE + d];
        gw[0 * DD + d] = hv * a0[d];
        gw[1 * DD + d] = hv * a1[d];
        gw[2 * DD + d] = hv * a2[d];
        gw[3 * DD + d] = hv * a3[d];
    }
    __syncwarp();

    // ---- score phase: s_k[j] = dot(g_k, h[j]) ; lane owns j = lane + 32t ----
    float s0[JT], s1[JT], s2[JT], s3[JT];
#pragma unroll
    for (int t = 0; t < JT; ++t) { s0[t] = s1[t] = s2[t] = s3[t] = 0.f; }

#pragma unroll 5
    for (int c = 0; c < CC; ++c) {
        float4 g0 = *(const float4*)(gw + 0 * DD + 4 * c);
        float4 g1 = *(const float4*)(gw + 1 * DD + 4 * c);
        float4 g2 = *(const float4*)(gw + 2 * DD + 4 * c);
        float4 g3 = *(const float4*)(gw + 3 * DD + 4 * c);
#pragma unroll
        for (int t = 0; t < JT; ++t) {
            int j = lane + 32 * t;
            float4 hv = *(const float4*)(hs + j * HS_STRIDE + 4 * c);
            s0[t] += hv.x * g0.x + hv.y * g0.y + hv.z * g0.z + hv.w * g0.w;
            s1[t] += hv.x * g1.x + hv.y * g1.y + hv.z * g1.z + hv.w * g1.w;
            s2[t] += hv.x * g2.x + hv.y * g2.y + hv.z * g2.z + hv.w * g2.w;
            s3[t] += hv.x * g3.x + hv.y * g3.y + hv.z * g3.z + hv.w * g3.w;
        }
    }

    // ---- adj select + leaky_relu ----
    const int* adjrow = adj + ((size_t)b * NN + i) * NN;
    float alpha[JT];
#pragma unroll
    for (int t = 0; t < JT; ++t) {
        int j = lane + 32 * t;
        float v = NEGV;
        if (j < NN) {
            int a = adjrow[j];
            float e = s0[t];
            e = (a == 2) ? s1[t] : e;
            e = (a == 3) ? s2[t] : e;
            e = (a == 4) ? s3[t] : e;
            e = (e >= 0.f) ? e : 0.2f * e;
            v = (a >= 1 && a <= 4) ? e : NEGV;
        }
        alpha[t] = v;
    }

    // ---- softmax over j (warp-wide) ----
    float m = alpha[0];
#pragma unroll
    for (int t = 1; t < JT; ++t) m = fmaxf(m, alpha[t]);
#pragma unroll
    for (int off = 16; off > 0; off >>= 1)
        m = fmaxf(m, __shfl_xor_sync(0xffffffffu, m, off));

    float p[JT];
    float sum = 0.f;
#pragma unroll
    for (int t = 0; t < JT; ++t) {
        int j = lane + 32 * t;
        float e = (j < NN) ? expf(alpha[t] - m) : 0.f;
        p[t] = e;
        sum += e;
    }
#pragma unroll
    for (int off = 16; off > 0; off >>= 1)
        sum += __shfl_xor_sync(0xffffffffu, sum, off);
    float rinv = 1.f / sum;

    // ---- aggregation: out[i][d] = (1/sum) * sum_j p_j * h[j][d] ----
    // lane owns d-chunk 4*lane..4*lane+3 (lanes 0..24 active)
    float4 acc = make_float4(0.f, 0.f, 0.f, 0.f);
#pragma unroll 1
    for (int t = 0; t < JT; ++t) {
        float pt = p[t];
        int base = 32 * t;
        int cnt  = (NN - base) < 32 ? (NN - base) : 32;
#pragma unroll 8
        for (int l = 0; l < cnt; ++l) {
            float pj = __shfl_sync(0xffffffffu, pt, l);
            if (lane < CC) {
                float4 hv = *(const float4*)(hs + (base + l) * HS_STRIDE + 4 * lane);
                acc.x += pj * hv.x;
                acc.y += pj * hv.y;
                acc.z += pj * hv.z;
                acc.w += pj * hv.w;
            }
        }
    }

    if (lane < CC) {
        float4 r;
        r.x = acc.x * rinv; r.y = acc.y * rinv;
        r.z = acc.z * rinv; r.w = acc.w * rinv;
        *(float4*)(out + ((size_t)(b * NN + i)) * DD + 4 * lane) = r;
    }
}

extern "C" void kernel_launch(void* const* d_in, const int* in_sizes, int n_in,
                              void* d_out, int out_size)
{
    const int*   inputs = (const int*)d_in[0];
    const int*   adj    = (const int*)d_in[1];
    // d_in[2] = mask_item (unused by reference)
    const float* emb    = (const float*)d_in[3];
    const float* a0     = (const float*)d_in[4];
    const float* a1     = (const float*)d_in[5];
    const float* a2     = (const float*)d_in[6];
    const float* a3     = (const float*)d_in[7];
    float*       out    = (float*)d_out;

    cudaFuncSetAttribute(gnn_agg_kernel,
                         cudaFuncAttributeMaxDynamicSharedMemorySize,
                         SMEM_BYTES);

    dim3 grid(NN / IT, BB);   // 25 x 32 = 800 blocks
    gnn_agg_kernel<<<grid, 256, SMEM_BYTES>>>(inputs, adj, emb,
                                              a0, a1, a2, a3, out);
}

// round 2
// speedup vs baseline: 1.0511x; 1.0511x over previous
#include <cuda_runtime.h>

typedef unsigned long long ull;

// Problem constants (fixed by the dataset)
#define BB 32
#define NN 200
#define DD 100
#define IT 8              // i-rows per block (one warp per row)
#define JT 7              // ceil(N/32) j-slots per lane
#define CC (DD/4)         // 25 float4 chunks per row
#define HS_STRIDE 108     // padded row stride in floats: phase-conflict-free LDS.128
#define NPAD 224          // padded row count so j = lane + 32t is always in-bounds
#define NEGV (-9e15f)

#define SMEM_BYTES (NPAD*HS_STRIDE*4 + IT*4*DD*4)

// packed f32x2 FMA: d = a*b + c  (two fp32 lanes per instruction -> SASS FFMA2)
#define FMA2(d, a, b, c) \
    asm("fma.rn.f32x2 %0, %1, %2, %3;" : "=l"(d) : "l"(a), "l"(b), "l"(c))

__device__ __forceinline__ float2 unpack2(ull v) {
    float2 f;
    asm("mov.b64 {%0, %1}, %2;" : "=f"(f.x), "=f"(f.y) : "l"(v));
    return f;
}
__device__ __forceinline__ ull pack_dup(float v) {
    ull r;
    asm("mov.b64 %0, {%1, %1};" : "=l"(r) : "f"(v));
    return r;
}

__global__ __launch_bounds__(256, 2)
void gnn_agg_kernel(const int* __restrict__ inputs,
                    const int* __restrict__ adj,
                    const float* __restrict__ emb,
                    const float* __restrict__ a0,
                    const float* __restrict__ a1,
                    const float* __restrict__ a2,
                    const float* __restrict__ a3,
                    float* __restrict__ out)
{
    extern __shared__ float sm[];
    float* hs = sm;                          // [NPAD][HS_STRIDE]
    float* gg = sm + NPAD * HS_STRIDE;       // [IT][4][DD]
    __shared__ int ids[NN];

    const int b    = blockIdx.y;
    const int i0   = blockIdx.x * IT;
    const int tid  = threadIdx.x;
    const int w    = tid >> 5;
    const int lane = tid & 31;
    const int i    = i0 + w;

    // ---- prefetch adj row into registers (hide DRAM/L2 latency behind gather) ----
    const int* adjrow = adj + ((size_t)b * NN + i) * NN;
    int av[JT];
#pragma unroll
    for (int t = 0; t < JT; ++t) {
        int j = lane + 32 * t;
        av[t] = (j < NN) ? adjrow[j] : 0;
    }

    // ---- load item ids for this batch ----
    if (tid < NN) ids[tid] = inputs[b * NN + tid];
    __syncthreads();

    // ---- gather h[b] into shared (padded layout) ----
    for (int u = tid; u < NN * CC; u += 256) {
        int j = u / CC, c = u - j * CC;
        float4 v = *(const float4*)(emb + (size_t)ids[j] * DD + 4 * c);
        *(float4*)(hs + j * HS_STRIDE + 4 * c) = v;
    }
    // zero pad rows [NN, NPAD)
    for (int u = tid; u < (NPAD - NN) * CC; u += 256) {
        int j = NN + u / CC, c = u - (u / CC) * CC;
        *(float4*)(hs + j * HS_STRIDE + 4 * c) = make_float4(0.f, 0.f, 0.f, 0.f);
    }
    __syncthreads();

    // ---- g_k[d] = h[i][d] * a_k[d] (per-warp, broadcast-read later) ----
    float* gw = gg + w * 4 * DD;
    for (int d = lane; d < DD; d += 32) {
        float hv = hs[i * HS_STRIDE + d];
        gw[0 * DD + d] = hv * a0[d];
        gw[1 * DD + d] = hv * a1[d];
        gw[2 * DD + d] = hv * a2[d];
        gw[3 * DD + d] = hv * a3[d];
    }
    __syncwarp();

    // ---- score phase: s_k[j] = dot(g_k, h[j]), packed f32x2 over d-pairs ----
    ull s0[JT], s1[JT], s2[JT], s3[JT];
#pragma unroll
    for (int t = 0; t < JT; ++t) { s0[t] = s1[t] = s2[t] = s3[t] = 0ull; }

#pragma unroll 5
    for (int c = 0; c < CC; ++c) {
        ulonglong2 g0 = *(const ulonglong2*)(gw + 0 * DD + 4 * c);
        ulonglong2 g1 = *(const ulonglong2*)(gw + 1 * DD + 4 * c);
        ulonglong2 g2 = *(const ulonglong2*)(gw + 2 * DD + 4 * c);
        ulonglong2 g3 = *(const ulonglong2*)(gw + 3 * DD + 4 * c);
#pragma unroll
        for (int t = 0; t < JT; ++t) {
            int j = lane + 32 * t;
            ulonglong2 hv = *(const ulonglong2*)(hs + j * HS_STRIDE + 4 * c);
            FMA2(s0[t], hv.x, g0.x, s0[t]);
            FMA2(s0[t], hv.y, g0.y, s0[t]);
            FMA2(s1[t], hv.x, g1.x, s1[t]);
            FMA2(s1[t], hv.y, g1.y, s1[t]);
            FMA2(s2[t], hv.x, g2.x, s2[t]);
            FMA2(s2[t], hv.y, g2.y, s2[t]);
            FMA2(s3[t], hv.x, g3.x, s3[t]);
            FMA2(s3[t], hv.y, g3.y, s3[t]);
        }
    }

    // ---- adj select + leaky_relu ----
    float alpha[JT];
#pragma unroll
    for (int t = 0; t < JT; ++t) {
        int j = lane + 32 * t;
        float v = NEGV;
        if (j < NN) {
            int a = av[t];
            float2 f0 = unpack2(s0[t]);
            float2 f1 = unpack2(s1[t]);
            float2 f2 = unpack2(s2[t]);
            float2 f3 = unpack2(s3[t]);
            float e = f0.x + f0.y;
            e = (a == 2) ? (f1.x + f1.y) : e;
            e = (a == 3) ? (f2.x + f2.y) : e;
            e = (a == 4) ? (f3.x + f3.y) : e;
            e = (e >= 0.f) ? e : 0.2f * e;
            v = (a >= 1 && a <= 4) ? e : NEGV;
        }
        alpha[t] = v;
    }

    // ---- softmax over j (warp-wide) ----
    float m = alpha[0];
#pragma unroll
    for (int t = 1; t < JT; ++t) m = fmaxf(m, alpha[t]);
#pragma unroll
    for (int off = 16; off > 0; off >>= 1)
        m = fmaxf(m, __shfl_xor_sync(0xffffffffu, m, off));

    float p[JT];
    float sum = 0.f;
#pragma unroll
    for (int t = 0; t < JT; ++t) {
        int j = lane + 32 * t;
        float e = (j < NN) ? expf(alpha[t] - m) : 0.f;
        p[t] = e;
        sum += e;
    }
#pragma unroll
    for (int off = 16; off > 0; off >>= 1)
        sum += __shfl_xor_sync(0xffffffffu, sum, off);
    float rinv = 1.f / sum;
#pragma unroll
    for (int t = 0; t < JT; ++t) p[t] *= rinv;

    // ---- aggregation: out[i][d] = sum_j p_j * h[j][d] (packed f32x2) ----
    // lane owns d-chunk 4*lane..4*lane+3 (lanes 0..24 active)
    ull acc0 = 0ull, acc1 = 0ull;
#pragma unroll 1
    for (int t = 0; t < JT; ++t) {
        float pt = p[t];
        int base = 32 * t;
        int cnt  = (NN - base) < 32 ? (NN - base) : 32;
#pragma unroll 4
        for (int l = 0; l < cnt; ++l) {
            float pj = __shfl_sync(0xffffffffu, pt, l);
            ull pjj = pack_dup(pj);
            if (lane < CC) {
                ulonglong2 hv = *(const ulonglong2*)(hs + (base + l) * HS_STRIDE + 4 * lane);
                FMA2(acc0, pjj, hv.x, acc0);
                FMA2(acc1, pjj, hv.y, acc1);
            }
        }
    }

    if (lane < CC) {
        float2 r0 = unpack2(acc0);
        float2 r1 = unpack2(acc1);
        float4 r = make_float4(r0.x, r0.y, r1.x, r1.y);
        *(float4*)(out + ((size_t)(b * NN + i)) * DD + 4 * lane) = r;
    }
}

extern "C" void kernel_launch(void* const* d_in, const int* in_sizes, int n_in,
                              void* d_out, int out_size)
{
    const int*   inputs = (const int*)d_in[0];
    const int*   adj    = (const int*)d_in[1];
    // d_in[2] = mask_item (unused by reference)
    const float* emb    = (const float*)d_in[3];
    const float* a0     = (const float*)d_in[4];
    const float* a1     = (const float*)d_in[5];
    const float* a2     = (const float*)d_in[6];
    const float* a3     = (const float*)d_in[7];
    float*       out    = (float*)d_out;

    cudaFuncSetAttribute(gnn_agg_kernel,
                         cudaFuncAttributeMaxDynamicSharedMemorySize,
                         SMEM_BYTES);

    dim3 grid(NN / IT, BB);   // 25 x 32 = 800 blocks
    gnn_agg_kernel<<<grid, 256, SMEM_BYTES>>>(inputs, adj, emb,
                                              a0, a1, a2, a3, out);
}

// round 3
// speedup vs baseline: 1.1521x; 1.0960x over previous
#include <cuda_runtime.h>

typedef unsigned long long ull;

// Problem constants (fixed by the dataset)
#define BB 32
#define NN 200
#define DD 100
#define IT 16             // i-rows per block (each of 8 warps owns 2 rows)
#define JT 7              // ceil(N/32) j-slots per lane
#define CC (DD/4)         // 25 float4 chunks per row
#define HSS 108           // padded row stride in floats: conflict-free LDS.128
#define NEGV (-9e15f)

#define GG_PER_WARP 800   // 2 i-rows * 4 k * 100 floats
#define SMEM_FLOATS (NN*HSS + 8*GG_PER_WARP)
#define SMEM_BYTES  (SMEM_FLOATS*4)   // 112000 B -> 2 blocks/SM

// packed f32x2 FMA: d = a*b + c  (SASS FFMA2)
#define FMA2(d, a, b, c) \
    asm("fma.rn.f32x2 %0, %1, %2, %3;" : "=l"(d) : "l"(a), "l"(b), "l"(c))

__device__ __forceinline__ float2 unpack2(ull v) {
    float2 f;
    asm("mov.b64 {%0, %1}, %2;" : "=f"(f.x), "=f"(f.y) : "l"(v));
    return f;
}
__device__ __forceinline__ ull pack_dup(float v) {
    ull r;
    asm("mov.b64 %0, {%1, %1};" : "=l"(r) : "f"(v));
    return r;
}

__global__ __launch_bounds__(256, 2)
void gnn_agg_kernel(const int* __restrict__ inputs,
                    const int* __restrict__ adj,
                    const float* __restrict__ emb,
                    const float* __restrict__ a0,
                    const float* __restrict__ a1,
                    const float* __restrict__ a2,
                    const float* __restrict__ a3,
                    float* __restrict__ out)
{
    extern __shared__ float sm[];
    float* hs = sm;                 // [NN][HSS]
    float* gg = sm + NN * HSS;      // [8 warps][2 i][4 k][DD]
    __shared__ int ids[NN];

    const int b    = blockIdx.y;
    const int i0   = blockIdx.x * IT;
    const int tid  = threadIdx.x;
    const int w    = tid >> 5;
    const int lane = tid & 31;

    const int iA  = i0 + w;               // always < NN (grid covers 13*16=208, iA<=199)
    const int iB  = i0 + 8 + w;
    const bool vB = (iB < NN);
    const int iBc = vB ? iB : (NN - 1);

    // ---- prefetch adj rows into registers ----
    const int* arA = adj + ((size_t)b * NN + iA)  * NN;
    const int* arB = adj + ((size_t)b * NN + iBc) * NN;
    int avA[JT], avB[JT];
#pragma unroll
    for (int t = 0; t < JT; ++t) {
        int j  = lane + 32 * t;
        int jc = (j < NN) ? j : 0;
        int xa = arA[jc], xb = arB[jc];
        avA[t] = (j < NN) ? xa : 0;
        avB[t] = (j < NN) ? xb : 0;
    }

    // ---- item ids ----
    if (tid < NN) ids[tid] = inputs[b * NN + tid];
    __syncthreads();

    // ---- gather h[b] into shared ----
    for (int u = tid; u < NN * CC; u += 256) {
        int j = u / CC, c = u - j * CC;
        *(float4*)(hs + j * HSS + 4 * c) =
            *(const float4*)(emb + (size_t)ids[j] * DD + 4 * c);
    }
    __syncthreads();

    // ---- stage g[k][d] = h[i][d]*a_k[d] for both i-rows of this warp ----
    float* gA = gg + w * GG_PER_WARP;
    float* gB = gA + 4 * DD;
    for (int d = lane; d < DD; d += 32) {
        float hA = hs[iA  * HSS + d];
        float hB = hs[iBc * HSS + d];
        float v0 = a0[d], v1 = a1[d], v2 = a2[d], v3 = a3[d];
        gA[0*DD + d] = hA * v0;  gA[1*DD + d] = hA * v1;
        gA[2*DD + d] = hA * v2;  gA[3*DD + d] = hA * v3;
        gB[0*DD + d] = hB * v0;  gB[1*DD + d] = hB * v1;
        gB[2*DD + d] = hB * v2;  gB[3*DD + d] = hB * v3;
    }
    __syncwarp();

    // ---- per-t pointers (selected-k g rows, clamped h rows) ----
    const float *hp[JT], *gpA[JT], *gpB[JT];
#pragma unroll
    for (int t = 0; t < JT; ++t) {
        int j  = lane + 32 * t;
        int jc = (j < NN) ? j : (NN - 1);
        hp[t] = hs + jc * HSS;
        int kA = avA[t] - 1; if ((unsigned)kA > 3u) kA = 0;
        int kB = avB[t] - 1; if ((unsigned)kB > 3u) kB = 0;
        gpA[t] = gA + kA * DD;
        gpB[t] = gB + kB * DD;
    }

    // ---- score phase: one selected dot product per (i,j), packed f32x2 ----
    ull sA[JT], sB[JT];
#pragma unroll
    for (int t = 0; t < JT; ++t) { sA[t] = 0ull; sB[t] = 0ull; }

#pragma unroll 5
    for (int c = 0; c < CC; ++c) {
#pragma unroll
        for (int t = 0; t < JT; ++t) {
            ulonglong2 hv = *(const ulonglong2*)(hp[t]  + 4 * c);
            ulonglong2 ga = *(const ulonglong2*)(gpA[t] + 4 * c);
            ulonglong2 gb = *(const ulonglong2*)(gpB[t] + 4 * c);
            FMA2(sA[t], hv.x, ga.x, sA[t]);
            FMA2(sA[t], hv.y, ga.y, sA[t]);
            FMA2(sB[t], hv.x, gb.x, sB[t]);
            FMA2(sB[t], hv.y, gb.y, sB[t]);
        }
    }

    // ---- leaky_relu + adj mask ----
    float alA[JT], alB[JT];
#pragma unroll
    for (int t = 0; t < JT; ++t) {
        int j = lane + 32 * t;
        float2 fa = unpack2(sA[t]);
        float2 fb = unpack2(sB[t]);
        float ea = fa.x + fa.y;
        float eb = fb.x + fb.y;
        ea = (ea >= 0.f) ? ea : 0.2f * ea;
        eb = (eb >= 0.f) ? eb : 0.2f * eb;
        bool okA = (j < NN) && (avA[t] >= 1) && (avA[t] <= 4);
        bool okB = (j < NN) && (avB[t] >= 1) && (avB[t] <= 4);
        alA[t] = okA ? ea : NEGV;
        alB[t] = okB ? eb : NEGV;
    }

    // ---- softmax over j for both rows (warp-wide) ----
    float mA = alA[0], mB = alB[0];
#pragma unroll
    for (int t = 1; t < JT; ++t) { mA = fmaxf(mA, alA[t]); mB = fmaxf(mB, alB[t]); }
#pragma unroll
    for (int off = 16; off > 0; off >>= 1) {
        mA = fmaxf(mA, __shfl_xor_sync(0xffffffffu, mA, off));
        mB = fmaxf(mB, __shfl_xor_sync(0xffffffffu, mB, off));
    }

    float pA[JT], pB[JT];
    float suA = 0.f, suB = 0.f;
#pragma unroll
    for (int t = 0; t < JT; ++t) {
        float ea = __expf(alA[t] - mA);
        float eb = __expf(alB[t] - mB);
        pA[t] = ea; suA += ea;
        pB[t] = eb; suB += eb;
    }
#pragma unroll
    for (int off = 16; off > 0; off >>= 1) {
        suA += __shfl_xor_sync(0xffffffffu, suA, off);
        suB += __shfl_xor_sync(0xffffffffu, suB, off);
    }
    float rA = 1.f / suA, rB = 1.f / suB;
#pragma unroll
    for (int t = 0; t < JT; ++t) { pA[t] *= rA; pB[t] *= rB; }

    // ---- aggregation: out[i][d] = sum_j p_j h[j][d], both rows share the hv stream ----
    ull aA0 = 0ull, aA1 = 0ull, aB0 = 0ull, aB1 = 0ull;
    const float* hrow = hs + 4 * lane;
#pragma unroll 1
    for (int t = 0; t < JT; ++t) {
        float ptA = pA[t], ptB = pB[t];
        int base = 32 * t;
        int cnt  = (NN - base) < 32 ? (NN - base) : 32;
#pragma unroll 4
        for (int l = 0; l < cnt; ++l) {
            ull qa = pack_dup(__shfl_sync(0xffffffffu, ptA, l));
            ull qb = pack_dup(__shfl_sync(0xffffffffu, ptB, l));
            if (lane < CC) {
                ulonglong2 hv = *(const ulonglong2*)(hrow + (base + l) * HSS);
                FMA2(aA0, qa, hv.x, aA0);
                FMA2(aA1, qa, hv.y, aA1);
                FMA2(aB0, qb, hv.x, aB0);
                FMA2(aB1, qb, hv.y, aB1);
            }
        }
    }

    if (lane < CC) {
        float2 r0 = unpack2(aA0), r1 = unpack2(aA1);
        *(float4*)(out + ((size_t)(b * NN + iA)) * DD + 4 * lane) =
            make_float4(r0.x, r0.y, r1.x, r1.y);
        if (vB) {
            float2 s0 = unpack2(aB0), s1 = unpack2(aB1);
            *(float4*)(out + ((size_t)(b * NN + iB)) * DD + 4 * lane) =
                make_float4(s0.x, s0.y, s1.x, s1.y);
        }
    }
}

extern "C" void kernel_launch(void* const* d_in, const int* in_sizes, int n_in,
                              void* d_out, int out_size)
{
    const int*   inputs = (const int*)d_in[0];
    const int*   adj    = (const int*)d_in[1];
    // d_in[2] = mask_item (unused by reference)
    const float* emb    = (const float*)d_in[3];
    const float* a0     = (const float*)d_in[4];
    const float* a1     = (const float*)d_in[5];
    const float* a2     = (const float*)d_in[6];
    const float* a3     = (const float*)d_in[7];
    float*       out    = (float*)d_out;

    cudaFuncSetAttribute(gnn_agg_kernel,
                         cudaFuncAttributeMaxDynamicSharedMemorySize,
                         SMEM_BYTES);

    dim3 grid((NN + IT - 1) / IT, BB);   // 13 x 32 = 416 blocks
    gnn_agg_kernel<<<grid, 256, SMEM_BYTES>>>(inputs, adj, emb,
                                              a0, a1, a2, a3, out);
}

// round 4
// speedup vs baseline: 1.3643x; 1.1842x over previous
#include <cuda_runtime.h>

typedef unsigned long long ull;

// Problem constants (fixed by the dataset)
#define BB 32
#define NN 200
#define DD 100
#define IT 8              // i-rows per block
#define CC 25             // float4 chunks per row (DD/4)
#define HSS 108           // hs row stride (floats): conflict-free for row-indexed LDS.128
#define PS  212           // p row stride (floats): 212%32=20 -> 8-lane column gather conflict-free
#define NEGV (-9e15f)

// smem layout (floats)
#define OFF_G  (NN*HSS)                 // g: [IT][4][DD] = 3200
#define OFF_P  (OFF_G + IT*4*DD)        // p: [IT][PS]    = 1696
#define SMEM_FLOATS (OFF_P + IT*PS)     // 26496 floats
#define SMEM_BYTES (SMEM_FLOATS*4)      // 105984 B -> 2 blocks/SM

// packed f32x2 FMA: d = a*b + c  (SASS FFMA2)
#define FMA2(d, a, b, c) \
    asm("fma.rn.f32x2 %0, %1, %2, %3;" : "=l"(d) : "l"(a), "l"(b), "l"(c))

__device__ __forceinline__ float2 unpack2(ull v) {
    float2 f;
    asm("mov.b64 {%0, %1}, %2;" : "=f"(f.x), "=f"(f.y) : "l"(v));
    return f;
}

__global__ __launch_bounds__(256, 2)
void gnn_agg_kernel(const int* __restrict__ inputs,
                    const int* __restrict__ adj,
                    const float* __restrict__ emb,
                    const float* __restrict__ a0,
                    const float* __restrict__ a1,
                    const float* __restrict__ a2,
                    const float* __restrict__ a3,
                    float* __restrict__ out)
{
    extern __shared__ float sm[];
    float* hs = sm;                 // [NN][HSS]
    float* g  = sm + OFF_G;         // [IT][4][DD]
    float* ps = sm + OFF_P;         // [IT][PS]
    __shared__ int ids[NN];

    const int b    = blockIdx.y;
    const int i0   = blockIdx.x * IT;
    const int tid  = threadIdx.x;
    const int w    = tid >> 5;
    const int lane = tid & 31;
    const bool act = (lane < 25);

    // this lane's j (lanes 25..31 shadow j of lane 24; masked at writes)
    const int j = w * 25 + (act ? lane : 24);

    // ---- prefetch adj column for this j across all 8 i (global, coalesced) ----
    int av[IT];
#pragma unroll
    for (int i = 0; i < IT; ++i)
        av[i] = adj[((size_t)b * NN + (i0 + i)) * NN + j];

    // ---- item ids ----
    if (tid < NN) ids[tid] = inputs[b * NN + tid];
    __syncthreads();

    // ---- gather h[b] into shared ----
    for (int u = tid; u < NN * CC; u += 256) {
        int r = u / CC, c = u - r * CC;
        *(float4*)(hs + r * HSS + 4 * c) =
            *(const float4*)(emb + (size_t)ids[r] * DD + 4 * c);
    }
    __syncthreads();

    // ---- block-shared g[i][k][d] = h[i0+i][d] * a_k[d] ----
    for (int u = tid; u < IT * DD; u += 256) {
        int i = u / DD, d = u - i * DD;
        float hv = hs[(i0 + i) * HSS + d];
        float* gi = g + i * 4 * DD;
        gi[0 * DD + d] = hv * a0[d];
        gi[1 * DD + d] = hv * a1[d];
        gi[2 * DD + d] = hv * a2[d];
        gi[3 * DD + d] = hv * a3[d];
    }
    __syncthreads();

    // ---- per-(lane,i): validity + selected-k g row ----
    unsigned validbits = 0;
    const float* gp[IT];
#pragma unroll
    for (int i = 0; i < IT; ++i) {
        int a = av[i];
        if (a >= 1 && a <= 4) validbits |= (1u << i);
        int kk = a - 1; if ((unsigned)kk > 3u) kk = 0;
        gp[i] = g + i * 4 * DD + kk * DD;
    }

    // ---- score: one selected dot per (i, j); h_j chunk loaded once per c ----
    ull s[IT];
#pragma unroll
    for (int i = 0; i < IT; ++i) s[i] = 0ull;

    const float* hrow = hs + j * HSS;
#pragma unroll 5
    for (int c = 0; c < CC; ++c) {
        ulonglong2 hv = *(const ulonglong2*)(hrow + 4 * c);
#pragma unroll
        for (int i = 0; i < IT; ++i) {
            ulonglong2 gv = *(const ulonglong2*)(gp[i] + 4 * c);
            FMA2(s[i], hv.x, gv.x, s[i]);
            FMA2(s[i], hv.y, gv.y, s[i]);
        }
    }

    // ---- leaky_relu + mask -> stage alpha in ps[i][j] ----
    if (act) {
#pragma unroll
        for (int i = 0; i < IT; ++i) {
            float2 f = unpack2(s[i]);
            float e = f.x + f.y;
            e = (e >= 0.f) ? e : 0.2f * e;
            ps[i * PS + j] = ((validbits >> i) & 1u) ? e : NEGV;
        }
    }
    __syncthreads();

    // ---- softmax: warp w owns row i = w ----
    {
        float al[7];
#pragma unroll
        for (int t = 0; t < 7; ++t) {
            int jj = lane + 32 * t;
            al[t] = (jj < NN) ? ps[w * PS + jj] : NEGV;
        }
        float m = al[0];
#pragma unroll
        for (int t = 1; t < 7; ++t) m = fmaxf(m, al[t]);
#pragma unroll
        for (int off = 16; off > 0; off >>= 1)
            m = fmaxf(m, __shfl_xor_sync(0xffffffffu, m, off));

        float pv[7];
        float sum = 0.f;
#pragma unroll
        for (int t = 0; t < 7; ++t) {
            int jj = lane + 32 * t;
            float e = (jj < NN) ? __expf(al[t] - m) : 0.f;
            pv[t] = e;
            sum += e;
        }
#pragma unroll
        for (int off = 16; off > 0; off >>= 1)
            sum += __shfl_xor_sync(0xffffffffu, sum, off);
        float rinv = 1.f / sum;
#pragma unroll
        for (int t = 0; t < 7; ++t) {
            int jj = lane + 32 * t;
            if (jj < NN) ps[w * PS + jj] = pv[t] * rinv;
        }
    }
    __syncthreads();

    // ---- aggregation: warp w streams its 25 j rows once, applies to all 8 i ----
    float4 acc[IT];
#pragma unroll
    for (int i = 0; i < IT; ++i) acc[i] = make_float4(0.f, 0.f, 0.f, 0.f);

    const int dl = act ? lane : 0;   // lane owns d-chunk 4*dl (lanes >=25 shadow lane 0)
#pragma unroll 5
    for (int jj = 0; jj < 25; ++jj) {
        int jb = w * 25 + jj;
        // lanes 0..7 gather p[i][jb] (conflict-free: PS%32=20), broadcast via shfl
        float pcol = (lane < IT) ? ps[lane * PS + jb] : 0.f;
        float4 hv = *(const float4*)(hs + jb * HSS + 4 * dl);
#pragma unroll
        for (int i = 0; i < IT; ++i) {
            float pj = __shfl_sync(0xffffffffu, pcol, i);
            acc[i].x += pj * hv.x;
            acc[i].y += pj * hv.y;
            acc[i].z += pj * hv.z;
            acc[i].w += pj * hv.w;
        }
    }
    __syncthreads();   // all warps done reading hs/ps

    // ---- one-shot cross-warp reduce through hs (now free) ----
    float* stg = hs;   // [7][IT][DD] = 5600 floats < NN*HSS
    if (w >= 1 && act) {
#pragma unroll
        for (int i = 0; i < IT; ++i)
            *(float4*)(stg + (w - 1) * (IT * DD) + i * DD + 4 * lane) = acc[i];
    }
    __syncthreads();

    if (w == 0 && act) {
#pragma unroll
        for (int ww = 0; ww < 7; ++ww) {
#pragma unroll
            for (int i = 0; i < IT; ++i) {
                float4 v = *(const float4*)(stg + ww * (IT * DD) + i * DD + 4 * lane);
                acc[i].x += v.x; acc[i].y += v.y;
                acc[i].z += v.z; acc[i].w += v.w;
            }
        }
#pragma unroll
        for (int i = 0; i < IT; ++i)
            *(float4*)(out + ((size_t)(b * NN + i0 + i)) * DD + 4 * lane) = acc[i];
    }
}

extern "C" void kernel_launch(void* const* d_in, const int* in_sizes, int n_in,
                              void* d_out, int out_size)
{
    const int*   inputs = (const int*)d_in[0];
    const int*   adj    = (const int*)d_in[1];
    // d_in[2] = mask_item (unused by reference)
    const float* emb    = (const float*)d_in[3];
    const float* a0     = (const float*)d_in[4];
    const float* a1     = (const float*)d_in[5];
    const float* a2     = (const float*)d_in[6];
    const float* a3     = (const float*)d_in[7];
    float*       out    = (float*)d_out;

    cudaFuncSetAttribute(gnn_agg_kernel,
                         cudaFuncAttributeMaxDynamicSharedMemorySize,
                         SMEM_BYTES);

    dim3 grid(NN / IT, BB);   // 25 x 32 = 800 blocks
    gnn_agg_kernel<<<grid, 256, SMEM_BYTES>>>(inputs, adj, emb,
                                              a0, a1, a2, a3, out);
}

// round 5
// speedup vs baseline: 1.3716x; 1.0054x over previous
#include <cuda_runtime.h>

typedef unsigned long long ull;

// Problem constants (fixed by the dataset)
#define BB 32
#define NN 200
#define DD 100
#define IT 8              // i-rows per block
#define CC 25             // float4 chunks per row (DD/4)
#define HSS 100           // hs row stride (floats): 4*lane bank walk -> conflict-free
#define PTS 12            // pt row stride (floats): 16B-aligned rows, 12*lane walk conflict-free
#define NEGV (-9e15f)

// smem layout (floats)
#define OFF_G   (NN*HSS)                 // g:  [IT][4][DD] = 3200
#define OFF_PT  (OFF_G + IT*4*DD)        // pt: [NN][PTS]   = 2400
#define SMEM_FLOATS (OFF_PT + NN*PTS)    // 25600 floats
#define SMEM_BYTES  (SMEM_FLOATS*4)      // 102400 B -> 2 blocks/SM

// packed f32x2 ops (SASS FFMA2 / FADD-pair)
#define FMA2(d, a, b, c) \
    asm("fma.rn.f32x2 %0, %1, %2, %3;" : "=l"(d) : "l"(a), "l"(b), "l"(c))
#define ADD2(d, a, b) \
    asm("add.rn.f32x2 %0, %1, %2;" : "=l"(d) : "l"(a), "l"(b))

__device__ __forceinline__ float2 unpack2(ull v) {
    float2 f;
    asm("mov.b64 {%0, %1}, %2;" : "=f"(f.x), "=f"(f.y) : "l"(v));
    return f;
}
__device__ __forceinline__ ull pack_dup(float v) {
    ull r;
    asm("mov.b64 %0, {%1, %1};" : "=l"(r) : "f"(v));
    return r;
}

__global__ __launch_bounds__(256, 2)
void gnn_agg_kernel(const int* __restrict__ inputs,
                    const int* __restrict__ adj,
                    const float* __restrict__ emb,
                    const float* __restrict__ a0,
                    const float* __restrict__ a1,
                    const float* __restrict__ a2,
                    const float* __restrict__ a3,
                    float* __restrict__ out)
{
    extern __shared__ float sm[];
    float* hs = sm;                 // [NN][HSS]
    float* g  = sm + OFF_G;         // [IT][4][DD]
    float* pt = sm + OFF_PT;        // [NN][PTS] (only first 8 of each row used)
    __shared__ int ids[NN];

    const int b    = blockIdx.y;
    const int i0   = blockIdx.x * IT;
    const int tid  = threadIdx.x;
    const int w    = tid >> 5;
    const int lane = tid & 31;
    const bool act = (lane < 25);

    // this lane's j (lanes 25..31 shadow lane 24's j; masked at writes)
    const int j = w * 25 + (act ? lane : 24);

    // ---- prefetch adj column for this j across all 8 i (L2-hot, coalesced) ----
    int av[IT];
#pragma unroll
    for (int i = 0; i < IT; ++i)
        av[i] = adj[((size_t)b * NN + (i0 + i)) * NN + j];

    // ---- item ids ----
    if (tid < NN) ids[tid] = inputs[b * NN + tid];
    __syncthreads();

    // ---- gather h[b] into shared + stage g[i][k][d] (same barrier region) ----
    for (int u = tid; u < NN * CC; u += 256) {
        int r = u / CC, c = u - r * CC;
        *(float4*)(hs + r * HSS + 4 * c) =
            *(const float4*)(emb + (size_t)ids[r] * DD + 4 * c);
    }
    for (int u = tid; u < IT * DD; u += 256) {
        int i = u / DD, d = u - i * DD;
        float hv = emb[(size_t)ids[i0 + i] * DD + d];   // direct from L2
        float* gi = g + i * 4 * DD;
        gi[0 * DD + d] = hv * a0[d];
        gi[1 * DD + d] = hv * a1[d];
        gi[2 * DD + d] = hv * a2[d];
        gi[3 * DD + d] = hv * a3[d];
    }
    __syncthreads();

    // ---- per-(lane,i): validity + selected-k g row ----
    unsigned validbits = 0;
    const float* gp[IT];
#pragma unroll
    for (int i = 0; i < IT; ++i) {
        int a = av[i];
        if (a >= 1 && a <= 4) validbits |= (1u << i);
        int kk = a - 1; if ((unsigned)kk > 3u) kk = 0;
        gp[i] = g + i * 4 * DD + kk * DD;
    }

    // ---- score: one selected dot per (i, j); h_j chunk loaded once per c ----
    ull s[IT];
#pragma unroll
    for (int i = 0; i < IT; ++i) s[i] = 0ull;

    const float* hrow = hs + j * HSS;
#pragma unroll 5
    for (int c = 0; c < CC; ++c) {
        ulonglong2 hv = *(const ulonglong2*)(hrow + 4 * c);
#pragma unroll
        for (int i = 0; i < IT; ++i) {
            ulonglong2 gv = *(const ulonglong2*)(gp[i] + 4 * c);
            FMA2(s[i], hv.x, gv.x, s[i]);
            FMA2(s[i], hv.y, gv.y, s[i]);
        }
    }

    // ---- leaky_relu + mask -> stage alpha transposed: pt[j][i] ----
    if (act) {
        float e[IT];
#pragma unroll
        for (int i = 0; i < IT; ++i) {
            float2 f = unpack2(s[i]);
            float v = f.x + f.y;
            v = (v >= 0.f) ? v : 0.2f * v;
            e[i] = ((validbits >> i) & 1u) ? v : NEGV;
        }
        *(float4*)(pt + j * PTS)     = make_float4(e[0], e[1], e[2], e[3]);
        *(float4*)(pt + j * PTS + 4) = make_float4(e[4], e[5], e[6], e[7]);
    }
    __syncthreads();

    // ---- softmax: warp w owns row i = w (reads pt[jj][w], strided conflict-free) ----
    {
        float al[7];
#pragma unroll
        for (int t = 0; t < 7; ++t) {
            int jj = lane + 32 * t;
            al[t] = (jj < NN) ? pt[jj * PTS + w] : NEGV;
        }
        float m = al[0];
#pragma unroll
        for (int t = 1; t < 7; ++t) m = fmaxf(m, al[t]);
#pragma unroll
        for (int off = 16; off > 0; off >>= 1)
            m = fmaxf(m, __shfl_xor_sync(0xffffffffu, m, off));

        float pv[7];
        float sum = 0.f;
#pragma unroll
        for (int t = 0; t < 7; ++t) {
            int jj = lane + 32 * t;
            float e = (jj < NN) ? __expf(al[t] - m) : 0.f;
            pv[t] = e;
            sum += e;
        }
#pragma unroll
        for (int off = 16; off > 0; off >>= 1)
            sum += __shfl_xor_sync(0xffffffffu, sum, off);
        float rinv = 1.f / sum;
#pragma unroll
        for (int t = 0; t < 7; ++t) {
            int jj = lane + 32 * t;
            if (jj < NN) pt[jj * PTS + w] = pv[t] * rinv;
        }
    }
    __syncthreads();

    // ---- aggregation: warp w streams its 25 j rows once; p via broadcast LDS ----
    ull acc0[IT], acc1[IT];
#pragma unroll
    for (int i = 0; i < IT; ++i) { acc0[i] = 0ull; acc1[i] = 0ull; }

    const int dl = act ? lane : 0;   // lane owns d-chunk 4*dl
    const float* hbase = hs + 4 * dl;
#pragma unroll 5
    for (int jj = 0; jj < 25; ++jj) {
        int jb = w * 25 + jj;
        ulonglong2 hv = *(const ulonglong2*)(hbase + jb * HSS);
        float4 pA = *(const float4*)(pt + jb * PTS);        // p[i=0..3] broadcast
        float4 pB = *(const float4*)(pt + jb * PTS + 4);    // p[i=4..7] broadcast
        ull q;
        q = pack_dup(pA.x); FMA2(acc0[0], q, hv.x, acc0[0]); FMA2(acc1[0], q, hv.y, acc1[0]);
        q = pack_dup(pA.y); FMA2(acc0[1], q, hv.x, acc0[1]); FMA2(acc1[1], q, hv.y, acc1[1]);
        q = pack_dup(pA.z); FMA2(acc0[2], q, hv.x, acc0[2]); FMA2(acc1[2], q, hv.y, acc1[2]);
        q = pack_dup(pA.w); FMA2(acc0[3], q, hv.x, acc0[3]); FMA2(acc1[3], q, hv.y, acc1[3]);
        q = pack_dup(pB.x); FMA2(acc0[4], q, hv.x, acc0[4]); FMA2(acc1[4], q, hv.y, acc1[4]);
        q = pack_dup(pB.y); FMA2(acc0[5], q, hv.x, acc0[5]); FMA2(acc1[5], q, hv.y, acc1[5]);
        q = pack_dup(pB.z); FMA2(acc0[6], q, hv.x, acc0[6]); FMA2(acc1[6], q, hv.y, acc1[6]);
        q = pack_dup(pB.w); FMA2(acc0[7], q, hv.x, acc0[7]); FMA2(acc1[7], q, hv.y, acc1[7]);
    }
    __syncthreads();   // all warps done reading hs/pt

    // ---- one-shot cross-warp reduce through hs (now free) ----
    float* stg = hs;   // [7][IT][DD] = 5600 floats
    if (w >= 1 && act) {
#pragma unroll
        for (int i = 0; i < IT; ++i) {
            ulonglong2 v; v.x = acc0[i]; v.y = acc1[i];
            *(ulonglong2*)(stg + (w - 1) * (IT * DD) + i * DD + 4 * lane) = v;
        }
    }
    __syncthreads();

    if (w == 0 && act) {
#pragma unroll
        for (int ww = 0; ww < 7; ++ww) {
#pragma unroll
            for (int i = 0; i < IT; ++i) {
                ulonglong2 v = *(const ulonglong2*)(stg + ww * (IT * DD) + i * DD + 4 * lane);
                ADD2(acc0[i], acc0[i], v.x);
                ADD2(acc1[i], acc1[i], v.y);
            }
        }
#pragma unroll
        for (int i = 0; i < IT; ++i) {
            ulonglong2 v; v.x = acc0[i]; v.y = acc1[i];
            *(ulonglong2*)(out + ((size_t)(b * NN + i0 + i)) * DD + 4 * lane) = v;
        }
    }
}

extern "C" void kernel_launch(void* const* d_in, const int* in_sizes, int n_in,
                              void* d_out, int out_size)
{
    const int*   inputs = (const int*)d_in[0];
    const int*   adj    = (const int*)d_in[1];
    // d_in[2] = mask_item (unused by reference)
    const float* emb    = (const float*)d_in[3];
    const float* a0     = (const float*)d_in[4];
    const float* a1     = (const float*)d_in[5];
    const float* a2     = (const float*)d_in[6];
    const float* a3     = (const float*)d_in[7];
    float*       out    = (float*)d_out;

    cudaFuncSetAttribute(gnn_agg_kernel,
                         cudaFuncAttributeMaxDynamicSharedMemorySize,
                         SMEM_BYTES);

    dim3 grid(NN / IT, BB);   // 25 x 32 = 800 blocks
    gnn_agg_kernel<<<grid, 256, SMEM_BYTES>>>(inputs, adj, emb,
                                              a0, a1, a2, a3, out);
}

// round 6
// speedup vs baseline: 1.4984x; 1.0924x over previous
#include <cuda_runtime.h>

typedef unsigned long long ull;

// Problem constants (fixed by the dataset)
#define BB 32
#define NN 200
#define DD 100
#define IT 8              // i-rows per block
#define CC 25             // float4 chunks per row (DD/4)
#define PTS 12            // pt row stride (floats)
#define STGS 104          // staging row stride (floats), 16B aligned
#define NEGV (-9e15f)

// smem layout (floats): g | pt | stg   (~49KB total -> 3 blocks/SM)
#define OFF_PT  (IT*4*DD)                    // g:  [IT][4][DD] = 3200
#define OFF_STG (OFF_PT + NN*PTS)            // pt: [NN][PTS]   = 2400
#define SMEM_FLOATS (OFF_STG + IT*IT*STGS)   // stg:[IT][IT][STGS] = 6656
#define SMEM_BYTES  (SMEM_FLOATS*4)          // 49024 B

// packed f32x2 ops (SASS FFMA2 / FADD-pair)
#define FMA2(d, a, b, c) \
    asm("fma.rn.f32x2 %0, %1, %2, %3;" : "=l"(d) : "l"(a), "l"(b), "l"(c))
#define ADD2(d, a, b) \
    asm("add.rn.f32x2 %0, %1, %2;" : "=l"(d) : "l"(a), "l"(b))

__device__ __forceinline__ float2 unpack2(ull v) {
    float2 f;
    asm("mov.b64 {%0, %1}, %2;" : "=f"(f.x), "=f"(f.y) : "l"(v));
    return f;
}
__device__ __forceinline__ ull pack_dup(float v) {
    ull r;
    asm("mov.b64 %0, {%1, %1};" : "=l"(r) : "f"(v));
    return r;
}

__global__ __launch_bounds__(256, 3)
void gnn_agg_kernel(const int* __restrict__ inputs,
                    const int* __restrict__ adj,
                    const float* __restrict__ emb,
                    const float* __restrict__ a0,
                    const float* __restrict__ a1,
                    const float* __restrict__ a2,
                    const float* __restrict__ a3,
                    float* __restrict__ out)
{
    extern __shared__ float sm[];
    float* g   = sm;                 // [IT][4][DD]
    float* pt  = sm + OFF_PT;        // [NN][PTS] (first 8 of each row used)
    float* stg = sm + OFF_STG;       // [IT writers][IT i][STGS]
    __shared__ int ids[NN];

    const int b    = blockIdx.y;
    const int i0   = blockIdx.x * IT;
    const int tid  = threadIdx.x;
    const int w    = tid >> 5;
    const int lane = tid & 31;
    const bool act = (lane < 25);

    // this lane's j (lanes 25..31 shadow lane 24's j; masked at writes)
    const int j = w * 25 + (act ? lane : 24);

    // ---- prefetch adj column for this j across all 8 i (L2-hot, coalesced) ----
    int av[IT];
#pragma unroll
    for (int i = 0; i < IT; ++i)
        av[i] = adj[((size_t)b * NN + (i0 + i)) * NN + j];

    // ---- item ids ----
    if (tid < NN) ids[tid] = inputs[b * NN + tid];
    __syncthreads();

    // ---- stage g[i][k][d] = h[i0+i][d] * a_k[d] (h read from L2) ----
    for (int u = tid; u < IT * DD; u += 256) {
        int i = u / DD, d = u - i * DD;
        float hv = emb[(size_t)ids[i0 + i] * DD + d];
        float* gi = g + i * 4 * DD;
        gi[0 * DD + d] = hv * a0[d];
        gi[1 * DD + d] = hv * a1[d];
        gi[2 * DD + d] = hv * a2[d];
        gi[3 * DD + d] = hv * a3[d];
    }
    __syncthreads();

    // ---- per-(lane,i): validity + selected-k g row ----
    unsigned validbits = 0;
    const float* gp[IT];
#pragma unroll
    for (int i = 0; i < IT; ++i) {
        int a = av[i];
        if (a >= 1 && a <= 4) validbits |= (1u << i);
        int kk = a - 1; if ((unsigned)kk > 3u) kk = 0;
        gp[i] = g + i * 4 * DD + kk * DD;
    }

    // ---- score: one selected dot per (i, j); h_j streamed from L2 ----
    ull s[IT];
#pragma unroll
    for (int i = 0; i < IT; ++i) s[i] = 0ull;

    const float* hrow = emb + (size_t)ids[j] * DD;
#pragma unroll 5
    for (int c = 0; c < CC; ++c) {
        ulonglong2 hv = *(const ulonglong2*)(hrow + 4 * c);
#pragma unroll
        for (int i = 0; i < IT; ++i) {
            ulonglong2 gv = *(const ulonglong2*)(gp[i] + 4 * c);
            FMA2(s[i], hv.x, gv.x, s[i]);
            FMA2(s[i], hv.y, gv.y, s[i]);
        }
    }

    // ---- leaky_relu + mask -> stage alpha transposed: pt[j][i] ----
    if (act) {
        float e[IT];
#pragma unroll
        for (int i = 0; i < IT; ++i) {
            float2 f = unpack2(s[i]);
            float v = f.x + f.y;
            v = (v >= 0.f) ? v : 0.2f * v;
            e[i] = ((validbits >> i) & 1u) ? v : NEGV;
        }
        *(float4*)(pt + j * PTS)     = make_float4(e[0], e[1], e[2], e[3]);
        *(float4*)(pt + j * PTS + 4) = make_float4(e[4], e[5], e[6], e[7]);
    }
    __syncthreads();

    // ---- softmax: warp w owns row i = w ----
    {
        float al[7];
#pragma unroll
        for (int t = 0; t < 7; ++t) {
            int jj = lane + 32 * t;
            al[t] = (jj < NN) ? pt[jj * PTS + w] : NEGV;
        }
        float m = al[0];
#pragma unroll
        for (int t = 1; t < 7; ++t) m = fmaxf(m, al[t]);
#pragma unroll
        for (int off = 16; off > 0; off >>= 1)
            m = fmaxf(m, __shfl_xor_sync(0xffffffffu, m, off));

        float pv[7];
        float sum = 0.f;
#pragma unroll
        for (int t = 0; t < 7; ++t) {
            int jj = lane + 32 * t;
            float e = (jj < NN) ? __expf(al[t] - m) : 0.f;
            pv[t] = e;
            sum += e;
        }
#pragma unroll
        for (int off = 16; off > 0; off >>= 1)
            sum += __shfl_xor_sync(0xffffffffu, sum, off);
        float rinv = 1.f / sum;
#pragma unroll
        for (int t = 0; t < 7; ++t) {
            int jj = lane + 32 * t;
            if (jj < NN) pt[jj * PTS + w] = pv[t] * rinv;
        }
    }
    __syncthreads();

    // ---- aggregation: warp w streams its 25 j rows from L2; p via broadcast LDS ----
    ull acc0[IT], acc1[IT];
#pragma unroll
    for (int i = 0; i < IT; ++i) { acc0[i] = 0ull; acc1[i] = 0ull; }

    const int dl = act ? lane : 24;   // lane owns d-chunk 4*dl (shadow lanes share 24)
#pragma unroll 5
    for (int jj = 0; jj < 25; ++jj) {
        int jb = w * 25 + jj;
        const float* hj = emb + (size_t)ids[jb] * DD;         // ids broadcast LDS
        ulonglong2 hv = *(const ulonglong2*)(hj + 4 * dl);    // L2-hot LDG.128
        float4 pA = *(const float4*)(pt + jb * PTS);          // p[i=0..3] broadcast
        float4 pB = *(const float4*)(pt + jb * PTS + 4);      // p[i=4..7] broadcast
        ull q;
        q = pack_dup(pA.x); FMA2(acc0[0], q, hv.x, acc0[0]); FMA2(acc1[0], q, hv.y, acc1[0]);
        q = pack_dup(pA.y); FMA2(acc0[1], q, hv.x, acc0[1]); FMA2(acc1[1], q, hv.y, acc1[1]);
        q = pack_dup(pA.z); FMA2(acc0[2], q, hv.x, acc0[2]); FMA2(acc1[2], q, hv.y, acc1[2]);
        q = pack_dup(pA.w); FMA2(acc0[3], q, hv.x, acc0[3]); FMA2(acc1[3], q, hv.y, acc1[3]);
        q = pack_dup(pB.x); FMA2(acc0[4], q, hv.x, acc0[4]); FMA2(acc1[4], q, hv.y, acc1[4]);
        q = pack_dup(pB.y); FMA2(acc0[5], q, hv.x, acc0[5]); FMA2(acc1[5], q, hv.y, acc1[5]);
        q = pack_dup(pB.z); FMA2(acc0[6], q, hv.x, acc0[6]); FMA2(acc1[6], q, hv.y, acc1[6]);
        q = pack_dup(pB.w); FMA2(acc0[7], q, hv.x, acc0[7]); FMA2(acc1[7], q, hv.y, acc1[7]);
    }

    // ---- parallel cross-warp reduce: everyone stages, warp w reduces row i=w ----
    if (act) {
#pragma unroll
        for (int i = 0; i < IT; ++i) {
            ulonglong2 v; v.x = acc0[i]; v.y = acc1[i];
            *(ulonglong2*)(stg + (w * IT + i) * STGS + 4 * lane) = v;
        }
    }
    __syncthreads();

    if (act) {
        ull r0 = 0ull, r1 = 0ull;
#pragma unroll
        for (int ww = 0; ww < IT; ++ww) {
            ulonglong2 v = *(const ulonglong2*)(stg + (ww * IT + w) * STGS + 4 * lane);
            ADD2(r0, r0, v.x);
            ADD2(r1, r1, v.y);
        }
        ulonglong2 o; o.x = r0; o.y = r1;
        *(ulonglong2*)(out + ((size_t)(b * NN + i0 + w)) * DD + 4 * lane) = o;
    }
}

extern "C" void kernel_launch(void* const* d_in, const int* in_sizes, int n_in,
                              void* d_out, int out_size)
{
    const int*   inputs = (const int*)d_in[0];
    const int*   adj    = (const int*)d_in[1];
    // d_in[2] = mask_item (unused by reference)
    const float* emb    = (const float*)d_in[3];
    const float* a0     = (const float*)d_in[4];
    const float* a1     = (const float*)d_in[5];
    const float* a2     = (const float*)d_in[6];
    const float* a3     = (const float*)d_in[7];
    float*       out    = (float*)d_out;

    cudaFuncSetAttribute(gnn_agg_kernel,
                         cudaFuncAttributeMaxDynamicSharedMemorySize,
                         SMEM_BYTES);

    dim3 grid(NN / IT, BB);   // 25 x 32 = 800 blocks
    gnn_agg_kernel<<<grid, 256, SMEM_BYTES>>>(inputs, adj, emb,
                                              a0, a1, a2, a3, out);
}

// round 7
// speedup vs baseline: 1.6934x; 1.1301x over previous
#include <cuda_runtime.h>

typedef unsigned long long ull;

// Problem constants (fixed by the dataset)
#define BB 32
#define NN 200
#define DD 100
#define IT 8              // i-rows per block
#define CC 25             // float4 chunks per row (DD/4)
#define PTS 12            // pt row stride (floats)
#define STGS 104          // staging row stride (floats), 16B aligned
#define NEGV (-9e15f)

// smem layout (floats): g | pt | stg   (~49KB total -> 3 blocks/SM)
#define G_FLOATS (IT*CC*16)                  // g interleaved: [IT][CC][4k][4] = 3200
#define OFF_PT  (G_FLOATS)
#define OFF_STG (OFF_PT + NN*PTS)            // pt: [NN][PTS] = 2400
#define SMEM_FLOATS (OFF_STG + IT*IT*STGS)   // stg:[IT][IT][STGS] = 6656
#define SMEM_BYTES  (SMEM_FLOATS*4)          // 49024 B

// packed f32x2 ops (SASS FFMA2 / FADD-pair)
#define FMA2(d, a, b, c) \
    asm("fma.rn.f32x2 %0, %1, %2, %3;" : "=l"(d) : "l"(a), "l"(b), "l"(c))
#define ADD2(d, a, b) \
    asm("add.rn.f32x2 %0, %1, %2;" : "=l"(d) : "l"(a), "l"(b))

__device__ __forceinline__ float2 unpack2(ull v) {
    float2 f;
    asm("mov.b64 {%0, %1}, %2;" : "=f"(f.x), "=f"(f.y) : "l"(v));
    return f;
}
__device__ __forceinline__ ull pack_dup(float v) {
    ull r;
    asm("mov.b64 %0, {%1, %1};" : "=l"(r) : "f"(v));
    return r;
}

// Transposed gathered embeddings: ht[b][c][j][4 floats]  (2.56 MB scratch)
__device__ float ht_scratch[(size_t)BB * CC * NN * 4];

__global__ void transpose_kernel(const int* __restrict__ inputs,
                                 const float* __restrict__ emb)
{
    const int c = blockIdx.x;      // chunk 0..24
    const int b = blockIdx.y;      // batch
    const int j = threadIdx.x;     // 0..255, 200 active
    if (j < NN) {
        int id = inputs[b * NN + j];
        float4 v = *(const float4*)(emb + (size_t)id * DD + 4 * c);
        *(float4*)(ht_scratch + (((size_t)b * CC + c) * NN + j) * 4) = v;
    }
}

__global__ __launch_bounds__(256, 3)
void gnn_agg_kernel(const int* __restrict__ inputs,
                    const int* __restrict__ adj,
                    const float* __restrict__ emb,
                    const float* __restrict__ a0,
                    const float* __restrict__ a1,
                    const float* __restrict__ a2,
                    const float* __restrict__ a3,
                    float* __restrict__ out)
{
    extern __shared__ float sm[];
    float* g   = sm;                 // interleaved: [(i*25+c)*16 + k*4 + r]
    float* pt  = sm + OFF_PT;        // [NN][PTS] (first 8 of each row used)
    float* stg = sm + OFF_STG;       // [IT writers][IT i][STGS]
    __shared__ int ids[NN];

    const int b    = blockIdx.y;
    const int i0   = blockIdx.x * IT;
    const int tid  = threadIdx.x;
    const int w    = tid >> 5;
    const int lane = tid & 31;
    const bool act = (lane < 25);

    // this lane's j (lanes 25..31 shadow lane 24's j; masked at writes)
    const int j = w * 25 + (act ? lane : 24);

    // ---- prefetch adj column for this j across all 8 i (L2-hot, coalesced) ----
    int av[IT];
#pragma unroll
    for (int i = 0; i < IT; ++i)
        av[i] = adj[((size_t)b * NN + (i0 + i)) * NN + j];

    // ---- item ids ----
    if (tid < NN) ids[tid] = inputs[b * NN + tid];
    __syncthreads();

    // ---- stage g (interleaved): g[(i*25+c)*16 + k*4 + r] = h_i[d]*a_k[d] ----
    for (int u = tid; u < IT * DD; u += 256) {
        int i = u / DD, d = u - i * DD;
        int c = d >> 2, r = d & 3;
        float hv = emb[(size_t)ids[i0 + i] * DD + d];
        float* gd = g + (i * CC + c) * 16 + r;
        gd[0]  = hv * a0[d];
        gd[4]  = hv * a1[d];
        gd[8]  = hv * a2[d];
        gd[12] = hv * a3[d];
    }
    __syncthreads();

    // ---- per-(lane,i): validity + selected-k offset into interleaved g ----
    unsigned validbits = 0;
    int goff[IT];
#pragma unroll
    for (int i = 0; i < IT; ++i) {
        int a = av[i];
        if (a >= 1 && a <= 4) validbits |= (1u << i);
        int kk = a - 1; if ((unsigned)kk > 3u) kk = 0;
        goff[i] = i * (CC * 16) + kk * 4;
    }

    // ---- score: one selected dot per (i, j); h_j from transposed scratch ----
    ull s[IT];
#pragma unroll
    for (int i = 0; i < IT; ++i) s[i] = 0ull;

    const float* htb = ht_scratch + ((size_t)b * CC * NN + j) * 4;
#pragma unroll 5
    for (int c = 0; c < CC; ++c) {
        ulonglong2 hv = *(const ulonglong2*)(htb + (size_t)c * NN * 4);
        const float* gc = g + c * 16;
#pragma unroll
        for (int i = 0; i < IT; ++i) {
            ulonglong2 gv = *(const ulonglong2*)(gc + goff[i]);
            FMA2(s[i], hv.x, gv.x, s[i]);
            FMA2(s[i], hv.y, gv.y, s[i]);
        }
    }

    // ---- leaky_relu + mask -> stage alpha transposed: pt[j][i] ----
    if (act) {
        float e[IT];
#pragma unroll
        for (int i = 0; i < IT; ++i) {
            float2 f = unpack2(s[i]);
            float v = f.x + f.y;
            v = (v >= 0.f) ? v : 0.2f * v;
            e[i] = ((validbits >> i) & 1u) ? v : NEGV;
        }
        *(float4*)(pt + j * PTS)     = make_float4(e[0], e[1], e[2], e[3]);
        *(float4*)(pt + j * PTS + 4) = make_float4(e[4], e[5], e[6], e[7]);
    }
    __syncthreads();

    // ---- softmax: warp w owns row i = w ----
    {
        float al[7];
#pragma unroll
        for (int t = 0; t < 7; ++t) {
            int jj = lane + 32 * t;
            al[t] = (jj < NN) ? pt[jj * PTS + w] : NEGV;
        }
        float m = al[0];
#pragma unroll
        for (int t = 1; t < 7; ++t) m = fmaxf(m, al[t]);
#pragma unroll
        for (int off = 16; off > 0; off >>= 1)
            m = fmaxf(m, __shfl_xor_sync(0xffffffffu, m, off));

        float pv[7];
        float sum = 0.f;
#pragma unroll
        for (int t = 0; t < 7; ++t) {
            int jj = lane + 32 * t;
            float e = (jj < NN) ? __expf(al[t] - m) : 0.f;
            pv[t] = e;
            sum += e;
        }
#pragma unroll
        for (int off = 16; off > 0; off >>= 1)
            sum += __shfl_xor_sync(0xffffffffu, sum, off);
        float rinv = 1.f / sum;
#pragma unroll
        for (int t = 0; t < 7; ++t) {
            int jj = lane + 32 * t;
            if (jj < NN) pt[jj * PTS + w] = pv[t] * rinv;
        }
    }
    __syncthreads();

    // ---- aggregation: warp w streams its 25 j rows from L2; p via broadcast LDS ----
    ull acc0[IT], acc1[IT];
#pragma unroll
    for (int i = 0; i < IT; ++i) { acc0[i] = 0ull; acc1[i] = 0ull; }

    const int dl = act ? lane : 24;   // lane owns d-chunk 4*dl (shadow lanes share 24)
#pragma unroll 5
    for (int jj = 0; jj < 25; ++jj) {
        int jb = w * 25 + jj;
        const float* hj = emb + (size_t)ids[jb] * DD;         // ids broadcast LDS
        ulonglong2 hv = *(const ulonglong2*)(hj + 4 * dl);    // L2-hot, 4-line burst
        float4 pA = *(const float4*)(pt + jb * PTS);          // p[i=0..3] broadcast
        float4 pB = *(const float4*)(pt + jb * PTS + 4);      // p[i=4..7] broadcast
        ull q;
        q = pack_dup(pA.x); FMA2(acc0[0], q, hv.x, acc0[0]); FMA2(acc1[0], q, hv.y, acc1[0]);
        q = pack_dup(pA.y); FMA2(acc0[1], q, hv.x, acc0[1]); FMA2(acc1[1], q, hv.y, acc1[1]);
        q = pack_dup(pA.z); FMA2(acc0[2], q, hv.x, acc0[2]); FMA2(acc1[2], q, hv.y, acc1[2]);
        q = pack_dup(pA.w); FMA2(acc0[3], q, hv.x, acc0[3]); FMA2(acc1[3], q, hv.y, acc1[3]);
        q = pack_dup(pB.x); FMA2(acc0[4], q, hv.x, acc0[4]); FMA2(acc1[4], q, hv.y, acc1[4]);
        q = pack_dup(pB.y); FMA2(acc0[5], q, hv.x, acc0[5]); FMA2(acc1[5], q, hv.y, acc1[5]);
        q = pack_dup(pB.z); FMA2(acc0[6], q, hv.x, acc0[6]); FMA2(acc1[6], q, hv.y, acc1[6]);
        q = pack_dup(pB.w); FMA2(acc0[7], q, hv.x, acc0[7]); FMA2(acc1[7], q, hv.y, acc1[7]);
    }

    // ---- parallel cross-warp reduce: everyone stages, warp w reduces row i=w ----
    if (act) {
#pragma unroll
        for (int i = 0; i < IT; ++i) {
            ulonglong2 v; v.x = acc0[i]; v.y = acc1[i];
            *(ulonglong2*)(stg + (w * IT + i) * STGS + 4 * lane) = v;
        }
    }
    __syncthreads();

    if (act) {
        ull r0 = 0ull, r1 = 0ull;
#pragma unroll
        for (int ww = 0; ww < IT; ++ww) {
            ulonglong2 v = *(const ulonglong2*)(stg + (ww * IT + w) * STGS + 4 * lane);
            ADD2(r0, r0, v.x);
            ADD2(r1, r1, v.y);
        }
        ulonglong2 o; o.x = r0; o.y = r1;
        *(ulonglong2*)(out + ((size_t)(b * NN + i0 + w)) * DD + 4 * lane) = o;
    }
}

extern "C" void kernel_launch(void* const* d_in, const int* in_sizes, int n_in,
                              void* d_out, int out_size)
{
    const int*   inputs = (const int*)d_in[0];
    const int*   adj    = (const int*)d_in[1];
    // d_in[2] = mask_item (unused by reference)
    const float* emb    = (const float*)d_in[3];
    const float* a0     = (const float*)d_in[4];
    const float* a1     = (const float*)d_in[5];
    const float* a2     = (const float*)d_in[6];
    const float* a3     = (const float*)d_in[7];
    float*       out    = (float*)d_out;

    cudaFuncSetAttribute(gnn_agg_kernel,
                         cudaFuncAttributeMaxDynamicSharedMemorySize,
                         SMEM_BYTES);

    // Phase 1: gather + transpose h into ht_scratch
    dim3 tg(CC, BB);     // 25 x 32
    transpose_kernel<<<tg, 256>>>(inputs, emb);

    // Phase 2: fused score/softmax/aggregate
    dim3 grid(NN / IT, BB);   // 25 x 32 = 800 blocks
    gnn_agg_kernel<<<grid, 256, SMEM_BYTES>>>(inputs, adj, emb,
                                              a0, a1, a2, a3, out);
}

// round 8
// speedup vs baseline: 1.6946x; 1.0007x over previous
#include <cuda_runtime.h>

typedef unsigned long long ull;

// Problem constants (fixed by the dataset)
#define BB 32
#define NN 200
#define DD 100
#define IT 8              // i-rows per block
#define CC 25             // float4 chunks per row (DD/4)
#define PTS 12            // pt row stride (floats)
#define STGS 104          // staging row stride (floats), 16B aligned
#define NEGV (-9e15f)

// smem layout (floats): g | pt | stg   (~49KB total -> target 4 blocks/SM)
#define G_FLOATS (IT*CC*16)                  // g interleaved: [IT][CC][4k][4] = 3200
#define OFF_PT  (G_FLOATS)
#define OFF_STG (OFF_PT + NN*PTS)            // pt: [NN][PTS] = 2400
#define SMEM_FLOATS (OFF_STG + IT*IT*STGS)   // stg:[IT][IT][STGS] = 6656
#define SMEM_BYTES  (SMEM_FLOATS*4)          // 49024 B

// packed f32x2 ops (SASS FFMA2 / FADD-pair)
#define FMA2(d, a, b, c) \
    asm("fma.rn.f32x2 %0, %1, %2, %3;" : "=l"(d) : "l"(a), "l"(b), "l"(c))
#define ADD2(d, a, b) \
    asm("add.rn.f32x2 %0, %1, %2;" : "=l"(d) : "l"(a), "l"(b))

__device__ __forceinline__ float2 unpack2(ull v) {
    float2 f;
    asm("mov.b64 {%0, %1}, %2;" : "=f"(f.x), "=f"(f.y) : "l"(v));
    return f;
}
__device__ __forceinline__ ull pack_dup(float v) {
    ull r;
    asm("mov.b64 %0, {%1, %1};" : "=l"(r) : "f"(v));
    return r;
}

// Transposed gathered embeddings: ht[b][c][j][4 floats]  (2.56 MB scratch)
__device__ float ht_scratch[(size_t)BB * CC * NN * 4];

__global__ void transpose_kernel(const int* __restrict__ inputs,
                                 const float* __restrict__ emb)
{
    const int c = blockIdx.x;      // chunk 0..24
    const int b = blockIdx.y;      // batch
    const int j = threadIdx.x;     // 0..255, 200 active
    if (j < NN) {
        int id = inputs[b * NN + j];
        float4 v = *(const float4*)(emb + (size_t)id * DD + 4 * c);
        *(float4*)(ht_scratch + (((size_t)b * CC + c) * NN + j) * 4) = v;
    }
}

__global__ __launch_bounds__(256, 4)
void gnn_agg_kernel(const int* __restrict__ inputs,
                    const int* __restrict__ adj,
                    const float* __restrict__ emb,
                    const float* __restrict__ a0,
                    const float* __restrict__ a1,
                    const float* __restrict__ a2,
                    const float* __restrict__ a3,
                    float* __restrict__ out)
{
    extern __shared__ float sm[];
    float* g   = sm;                 // interleaved: [(i*25+c)*16 + k*4 + r]
    float* pt  = sm + OFF_PT;        // [NN][PTS] (first 8 of each row used)
    float* stg = sm + OFF_STG;       // [IT writers][IT i][STGS]
    __shared__ int ids[NN];

    const int b    = blockIdx.y;
    const int i0   = blockIdx.x * IT;
    const int tid  = threadIdx.x;
    const int w    = tid >> 5;
    const int lane = tid & 31;
    const bool act = (lane < 25);

    // this lane's j (lanes 25..31 shadow lane 24's j; masked at writes)
    const int j = w * 25 + (act ? lane : 24);

    // ---- adj column for this j across 8 i -> packed nibbles (reg diet) ----
    unsigned validbits = 0;   // bit i: adj in [1,4]
    unsigned kbits = 0;       // nibble i: selected k (0 if invalid)
    {
        const int* ap = adj + ((size_t)b * NN) * NN + j;
#pragma unroll
        for (int i = 0; i < IT; ++i) {
            int a = ap[(size_t)(i0 + i) * NN];
            if (a >= 1 && a <= 4) validbits |= (1u << i);
            int kk = a - 1; if ((unsigned)kk > 3u) kk = 0;
            kbits |= ((unsigned)kk << (4 * i));
        }
    }

    // ---- item ids ----
    if (tid < NN) ids[tid] = inputs[b * NN + tid];
    __syncthreads();

    // ---- stage g (interleaved): g[(i*25+c)*16 + k*4 + r] = h_i[d]*a_k[d] ----
    for (int u = tid; u < IT * DD; u += 256) {
        int i = u / DD, d = u - i * DD;
        int c = d >> 2, r = d & 3;
        float hv = emb[(size_t)ids[i0 + i] * DD + d];
        float* gd = g + (i * CC + c) * 16 + r;
        gd[0]  = hv * a0[d];
        gd[4]  = hv * a1[d];
        gd[8]  = hv * a2[d];
        gd[12] = hv * a3[d];
    }
    __syncthreads();

    // ---- score: one selected dot per (i, j); h_j from transposed scratch ----
    ull s[IT];
#pragma unroll
    for (int i = 0; i < IT; ++i) s[i] = 0ull;

    const float* htb = ht_scratch + ((size_t)b * CC * NN + j) * 4;
#pragma unroll 5
    for (int c = 0; c < CC; ++c) {
        ulonglong2 hv = *(const ulonglong2*)(htb + (size_t)c * NN * 4);
        const float* gc = g + c * 16;
#pragma unroll
        for (int i = 0; i < IT; ++i) {
            // selected-k offset recomputed inline: i*(CC*16) + k*4
            int koff = (int)((kbits >> (4 * i)) & 0xFu) * 4;
            ulonglong2 gv = *(const ulonglong2*)(gc + i * (CC * 16) + koff);
            FMA2(s[i], hv.x, gv.x, s[i]);
            FMA2(s[i], hv.y, gv.y, s[i]);
        }
    }

    // ---- leaky_relu + mask -> stage alpha transposed: pt[j][i] ----
    if (act) {
        float e[IT];
#pragma unroll
        for (int i = 0; i < IT; ++i) {
            float2 f = unpack2(s[i]);
            float v = f.x + f.y;
            v = (v >= 0.f) ? v : 0.2f * v;
            e[i] = ((validbits >> i) & 1u) ? v : NEGV;
        }
        *(float4*)(pt + j * PTS)     = make_float4(e[0], e[1], e[2], e[3]);
        *(float4*)(pt + j * PTS + 4) = make_float4(e[4], e[5], e[6], e[7]);
    }
    __syncthreads();

    // ---- softmax: warp w owns row i = w ----
    {
        float al[7];
#pragma unroll
        for (int t = 0; t < 7; ++t) {
            int jj = lane + 32 * t;
            al[t] = (jj < NN) ? pt[jj * PTS + w] : NEGV;
        }
        float m = al[0];
#pragma unroll
        for (int t = 1; t < 7; ++t) m = fmaxf(m, al[t]);
#pragma unroll
        for (int off = 16; off > 0; off >>= 1)
            m = fmaxf(m, __shfl_xor_sync(0xffffffffu, m, off));

        float pv[7];
        float sum = 0.f;
#pragma unroll
        for (int t = 0; t < 7; ++t) {
            int jj = lane + 32 * t;
            float e = (jj < NN) ? __expf(al[t] - m) : 0.f;
            pv[t] = e;
            sum += e;
        }
#pragma unroll
        for (int off = 16; off > 0; off >>= 1)
            sum += __shfl_xor_sync(0xffffffffu, sum, off);
        float rinv = 1.f / sum;
#pragma unroll
        for (int t = 0; t < 7; ++t) {
            int jj = lane + 32 * t;
            if (jj < NN) pt[jj * PTS + w] = pv[t] * rinv;
        }
    }
    __syncthreads();

    // ---- aggregation: warp w streams its 25 j rows from L2; p via broadcast LDS ----
    ull acc0[IT], acc1[IT];
#pragma unroll
    for (int i = 0; i < IT; ++i) { acc0[i] = 0ull; acc1[i] = 0ull; }

    const int dl = act ? lane : 24;   // lane owns d-chunk 4*dl (shadow lanes share 24)
#pragma unroll 5
    for (int jj = 0; jj < 25; ++jj) {
        int jb = w * 25 + jj;
        const float* hj = emb + (size_t)ids[jb] * DD;         // ids broadcast LDS
        ulonglong2 hv = *(const ulonglong2*)(hj + 4 * dl);    // L2-hot, 4-line burst
        float4 pA = *(const float4*)(pt + jb * PTS);          // p[i=0..3] broadcast
        float4 pB = *(const float4*)(pt + jb * PTS + 4);      // p[i=4..7] broadcast
        ull q;
        q = pack_dup(pA.x); FMA2(acc0[0], q, hv.x, acc0[0]); FMA2(acc1[0], q, hv.y, acc1[0]);
        q = pack_dup(pA.y); FMA2(acc0[1], q, hv.x, acc0[1]); FMA2(acc1[1], q, hv.y, acc1[1]);
        q = pack_dup(pA.z); FMA2(acc0[2], q, hv.x, acc0[2]); FMA2(acc1[2], q, hv.y, acc1[2]);
        q = pack_dup(pA.w); FMA2(acc0[3], q, hv.x, acc0[3]); FMA2(acc1[3], q, hv.y, acc1[3]);
        q = pack_dup(pB.x); FMA2(acc0[4], q, hv.x, acc0[4]); FMA2(acc1[4], q, hv.y, acc1[4]);
        q = pack_dup(pB.y); FMA2(acc0[5], q, hv.x, acc0[5]); FMA2(acc1[5], q, hv.y, acc1[5]);
        q = pack_dup(pB.z); FMA2(acc0[6], q, hv.x, acc0[6]); FMA2(acc1[6], q, hv.y, acc1[6]);
        q = pack_dup(pB.w); FMA2(acc0[7], q, hv.x, acc0[7]); FMA2(acc1[7], q, hv.y, acc1[7]);
    }

    // ---- parallel cross-warp reduce: everyone stages, warp w reduces row i=w ----
    if (act) {
#pragma unroll
        for (int i = 0; i < IT; ++i) {
            ulonglong2 v; v.x = acc0[i]; v.y = acc1[i];
            *(ulonglong2*)(stg + (w * IT + i) * STGS + 4 * lane) = v;
        }
    }
    __syncthreads();

    if (act) {
        ull r0 = 0ull, r1 = 0ull;
#pragma unroll
        for (int ww = 0; ww < IT; ++ww) {
            ulonglong2 v = *(const ulonglong2*)(stg + (ww * IT + w) * STGS + 4 * lane);
            ADD2(r0, r0, v.x);
            ADD2(r1, r1, v.y);
        }
        ulonglong2 o; o.x = r0; o.y = r1;
        *(ulonglong2*)(out + ((size_t)(b * NN + i0 + w)) * DD + 4 * lane) = o;
    }
}

extern "C" void kernel_launch(void* const* d_in, const int* in_sizes, int n_in,
                              void* d_out, int out_size)
{
    const int*   inputs = (const int*)d_in[0];
    const int*   adj    = (const int*)d_in[1];
    // d_in[2] = mask_item (unused by reference)
    const float* emb    = (const float*)d_in[3];
    const float* a0     = (const float*)d_in[4];
    const float* a1     = (const float*)d_in[5];
    const float* a2     = (const float*)d_in[6];
    const float* a3     = (const float*)d_in[7];
    float*       out    = (float*)d_out;

    cudaFuncSetAttribute(gnn_agg_kernel,
                         cudaFuncAttributeMaxDynamicSharedMemorySize,
                         SMEM_BYTES);

    // Phase 1: gather + transpose h into ht_scratch
    dim3 tg(CC, BB);     // 25 x 32
    transpose_kernel<<<tg, 256>>>(inputs, emb);

    // Phase 2: fused score/softmax/aggregate
    dim3 grid(NN / IT, BB);   // 25 x 32 = 800 blocks
    gnn_agg_kernel<<<grid, 256, SMEM_BYTES>>>(inputs, adj, emb,
                                              a0, a1, a2, a3, out);
}

// round 9
// speedup vs baseline: 2.0879x; 1.2321x over previous
#include <cuda_runtime.h>
#include <cuda_fp16.h>

typedef unsigned long long ull;

// Problem constants (fixed by the dataset)
#define BB 32
#define NN 200
#define DD 100
#define IT 8              // i-rows per block
#define C8 13             // 8-half chunks per row (ceil(100/8))
#define PTS 12            // pt row stride (floats)
#define STGS 104          // staging row stride (floats), 16B aligned
#define NEGV (-9e15f)

// smem layout (floats): g(fp16) | pt | stg
#define G_FLOATS (IT*C8*32)                  // g: [IT][C8][4k][8 halves] = 6656 halves = 3328 floats
#define OFF_PT  (G_FLOATS)
#define OFF_STG (OFF_PT + NN*PTS)            // pt: [NN][PTS] = 2400
#define SMEM_FLOATS (OFF_STG + IT*IT*STGS)   // stg:[IT][IT][STGS] = 6656
#define SMEM_BYTES  (SMEM_FLOATS*4)          // 49536 B -> 4 blocks/SM

// packed f32x2 ops (SASS FFMA2 / FADD-pair)
#define FMA2(d, a, b, c) \
    asm("fma.rn.f32x2 %0, %1, %2, %3;" : "=l"(d) : "l"(a), "l"(b), "l"(c))
#define ADD2(d, a, b) \
    asm("add.rn.f32x2 %0, %1, %2;" : "=l"(d) : "l"(a), "l"(b))

__device__ __forceinline__ float2 unpack2(ull v) {
    float2 f;
    asm("mov.b64 {%0, %1}, %2;" : "=f"(f.x), "=f"(f.y) : "l"(v));
    return f;
}
__device__ __forceinline__ ull pack_dup(float v) {
    ull r;
    asm("mov.b64 %0, {%1, %1};" : "=l"(r) : "f"(v));
    return r;
}

// fp16 transposed gathered embeddings: ht[b][c8][j][8 halves]  (1.33 MB)
__device__ __half ht_scratch[(size_t)BB * C8 * NN * 8];
// fp16 edge weights: ah[c8][k][8 halves]
__device__ __half ah_scratch[C8 * 4 * 8];

__global__ void transpose_kernel(const int* __restrict__ inputs,
                                 const float* __restrict__ emb,
                                 const float* __restrict__ a0,
                                 const float* __restrict__ a1,
                                 const float* __restrict__ a2,
                                 const float* __restrict__ a3)
{
    const int c8 = blockIdx.x;     // 0..12
    const int b  = blockIdx.y;     // batch
    const int j  = threadIdx.x;    // 0..255, 200 active
    if (j < NN) {
        int id = inputs[b * NN + j];
        const float* src = emb + (size_t)id * DD;
        __half h[8];
#pragma unroll
        for (int r = 0; r < 8; ++r) {
            int d = c8 * 8 + r;
            h[r] = __float2half(d < DD ? src[d] : 0.f);
        }
        *(uint4*)(ht_scratch + (((size_t)b * C8 + c8) * NN + j) * 8) = *(uint4*)h;
    }
    if (b == 0 && j < 4) {
        const float* ak = (j == 0) ? a0 : (j == 1) ? a1 : (j == 2) ? a2 : a3;
        __half h[8];
#pragma unroll
        for (int r = 0; r < 8; ++r) {
            int d = c8 * 8 + r;
            h[r] = __float2half(d < DD ? ak[d] : 0.f);
        }
        *(uint4*)(ah_scratch + (c8 * 4 + j) * 8) = *(uint4*)h;
    }
}

__global__ __launch_bounds__(256, 4)
void gnn_agg_kernel(const int* __restrict__ inputs,
                    const int* __restrict__ adj,
                    const float* __restrict__ emb,
                    float* __restrict__ out)
{
    extern __shared__ float sm[];
    __half* g  = (__half*)sm;        // [IT][C8][4k][8 halves], 128B per (i,c8)
    float* pt  = sm + OFF_PT;        // [NN][PTS] (first 8 of each row used)
    float* stg = sm + OFF_STG;       // [IT writers][IT i][STGS]
    __shared__ int ids[NN];

    const int b    = blockIdx.y;
    const int i0   = blockIdx.x * IT;
    const int tid  = threadIdx.x;
    const int w    = tid >> 5;
    const int lane = tid & 31;
    const bool act = (lane < 25);

    // this lane's j (lanes 25..31 shadow lane 24's j; masked at writes)
    const int j = w * 25 + (act ? lane : 24);

    // ---- adj column for this j across 8 i -> packed nibbles ----
    unsigned validbits = 0;   // bit i: adj in [1,4]
    unsigned kbits = 0;       // nibble i: selected k (0 if invalid)
    {
        const int* ap = adj + ((size_t)b * NN) * NN + j;
#pragma unroll
        for (int i = 0; i < IT; ++i) {
            int a = ap[(size_t)(i0 + i) * NN];
            if (a >= 1 && a <= 4) validbits |= (1u << i);
            int kk = a - 1; if ((unsigned)kk > 3u) kk = 0;
            kbits |= ((unsigned)kk << (4 * i));
        }
    }

    // ---- item ids ----
    if (tid < NN) ids[tid] = inputs[b * NN + tid];

    // ---- stage g (fp16): g[i][c8][k][8] = h_i[8d] * a_k[8d] ----
    if (tid < IT * C8) {
        int i = tid / C8, c8 = tid - i * C8;
        uint4 hraw = *(const uint4*)(ht_scratch +
                       (((size_t)b * C8 + c8) * NN + (i0 + i)) * 8);
        __half2 hh[4];
        *(uint4*)hh = hraw;
#pragma unroll
        for (int k = 0; k < 4; ++k) {
            uint4 araw = *(const uint4*)(ah_scratch + (c8 * 4 + k) * 8);
            __half2 aa[4];
            *(uint4*)aa = araw;
            __half2 p[4];
            p[0] = __hmul2(hh[0], aa[0]);
            p[1] = __hmul2(hh[1], aa[1]);
            p[2] = __hmul2(hh[2], aa[2]);
            p[3] = __hmul2(hh[3], aa[3]);
            *(uint4*)(g + (i * C8 + c8) * 64 + k * 8) = *(uint4*)p;
        }
    }
    __syncthreads();

    // ---- score: one selected dot per (i, j); fp16 HFMA2 ----
    __half2 s2[IT];
#pragma unroll
    for (int i = 0; i < IT; ++i) s2[i] = __float2half2_rn(0.f);

    const __half* htb = ht_scratch + ((size_t)b * C8 * NN + j) * 8;
#pragma unroll
    for (int c8 = 0; c8 < C8; ++c8) {
        uint4 hraw = *(const uint4*)(htb + (size_t)c8 * NN * 8);
        __half2 hh[4];
        *(uint4*)hh = hraw;
#pragma unroll
        for (int i = 0; i < IT; ++i) {
            int koff = (int)((kbits >> (4 * i)) & 0xFu) * 8;
            uint4 graw = *(const uint4*)(g + (i * C8 + c8) * 64 + koff);
            __half2 gg[4];
            *(uint4*)gg = graw;
            s2[i] = __hfma2(hh[0], gg[0], s2[i]);
            s2[i] = __hfma2(hh[1], gg[1], s2[i]);
            s2[i] = __hfma2(hh[2], gg[2], s2[i]);
            s2[i] = __hfma2(hh[3], gg[3], s2[i]);
        }
    }

    // ---- leaky_relu + mask -> stage alpha transposed: pt[j][i] ----
    if (act) {
        float e[IT];
#pragma unroll
        for (int i = 0; i < IT; ++i) {
            float2 f = __half22float2(s2[i]);
            float v = f.x + f.y;
            v = (v >= 0.f) ? v : 0.2f * v;
            e[i] = ((validbits >> i) & 1u) ? v : NEGV;
        }
        *(float4*)(pt + j * PTS)     = make_float4(e[0], e[1], e[2], e[3]);
        *(float4*)(pt + j * PTS + 4) = make_float4(e[4], e[5], e[6], e[7]);
    }
    __syncthreads();

    // ---- softmax: warp w owns row i = w ----
    {
        float al[7];
#pragma unroll
        for (int t = 0; t < 7; ++t) {
            int jj = lane + 32 * t;
            al[t] = (jj < NN) ? pt[jj * PTS + w] : NEGV;
        }
        float m = al[0];
#pragma unroll
        for (int t = 1; t < 7; ++t) m = fmaxf(m, al[t]);
#pragma unroll
        for (int off = 16; off > 0; off >>= 1)
            m = fmaxf(m, __shfl_xor_sync(0xffffffffu, m, off));

        float pv[7];
        float sum = 0.f;
#pragma unroll
        for (int t = 0; t < 7; ++t) {
            int jj = lane + 32 * t;
            float e = (jj < NN) ? __expf(al[t] - m) : 0.f;
            pv[t] = e;
            sum += e;
        }
#pragma unroll
        for (int off = 16; off > 0; off >>= 1)
            sum += __shfl_xor_sync(0xffffffffu, sum, off);
        float rinv = 1.f / sum;
#pragma unroll
        for (int t = 0; t < 7; ++t) {
            int jj = lane + 32 * t;
            if (jj < NN) pt[jj * PTS + w] = pv[t] * rinv;
        }
    }
    __syncthreads();

    // ---- aggregation (fp32): warp w streams its 25 j rows from L2 ----
    ull acc0[IT], acc1[IT];
#pragma unroll
    for (int i = 0; i < IT; ++i) { acc0[i] = 0ull; acc1[i] = 0ull; }

    const int dl = act ? lane : 24;   // lane owns d-chunk 4*dl
#pragma unroll 5
    for (int jj = 0; jj < 25; ++jj) {
        int jb = w * 25 + jj;
        const float* hj = emb + (size_t)ids[jb] * DD;         // ids broadcast LDS
        ulonglong2 hv = *(const ulonglong2*)(hj + 4 * dl);    // L2-hot LDG.128
        float4 pA = *(const float4*)(pt + jb * PTS);          // p[i=0..3] broadcast
        float4 pB = *(const float4*)(pt + jb * PTS + 4);      // p[i=4..7] broadcast
        ull q;
        q = pack_dup(pA.x); FMA2(acc0[0], q, hv.x, acc0[0]); FMA2(acc1[0], q, hv.y, acc1[0]);
        q = pack_dup(pA.y); FMA2(acc0[1], q, hv.x, acc0[1]); FMA2(acc1[1], q, hv.y, acc1[1]);
        q = pack_dup(pA.z); FMA2(acc0[2], q, hv.x, acc0[2]); FMA2(acc1[2], q, hv.y, acc1[2]);
        q = pack_dup(pA.w); FMA2(acc0[3], q, hv.x, acc0[3]); FMA2(acc1[3], q, hv.y, acc1[3]);
        q = pack_dup(pB.x); FMA2(acc0[4], q, hv.x, acc0[4]); FMA2(acc1[4], q, hv.y, acc1[4]);
        q = pack_dup(pB.y); FMA2(acc0[5], q, hv.x, acc0[5]); FMA2(acc1[5], q, hv.y, acc1[5]);
        q = pack_dup(pB.z); FMA2(acc0[6], q, hv.x, acc0[6]); FMA2(acc1[6], q, hv.y, acc1[6]);
        q = pack_dup(pB.w); FMA2(acc0[7], q, hv.x, acc0[7]); FMA2(acc1[7], q, hv.y, acc1[7]);
    }

    // ---- parallel cross-warp reduce: everyone stages, warp w reduces row i=w ----
    if (act) {
#pragma unroll
        for (int i = 0; i < IT; ++i) {
            ulonglong2 v; v.x = acc0[i]; v.y = acc1[i];
            *(ulonglong2*)(stg + (w * IT + i) * STGS + 4 * lane) = v;
        }
    }
    __syncthreads();

    if (act) {
        ull r0 = 0ull, r1 = 0ull;
#pragma unroll
        for (int ww = 0; ww < IT; ++ww) {
            ulonglong2 v = *(const ulonglong2*)(stg + (ww * IT + w) * STGS + 4 * lane);
            ADD2(r0, r0, v.x);
            ADD2(r1, r1, v.y);
        }
        ulonglong2 o; o.x = r0; o.y = r1;
        *(ulonglong2*)(out + ((size_t)(b * NN + i0 + w)) * DD + 4 * lane) = o;
    }
}

extern "C" void kernel_launch(void* const* d_in, const int* in_sizes, int n_in,
                              void* d_out, int out_size)
{
    const int*   inputs = (const int*)d_in[0];
    const int*   adj    = (const int*)d_in[1];
    // d_in[2] = mask_item (unused by reference)
    const float* emb    = (const float*)d_in[3];
    const float* a0     = (const float*)d_in[4];
    const float* a1     = (const float*)d_in[5];
    const float* a2     = (const float*)d_in[6];
    const float* a3     = (const float*)d_in[7];
    float*       out    = (float*)d_out;

    cudaFuncSetAttribute(gnn_agg_kernel,
                         cudaFuncAttributeMaxDynamicSharedMemorySize,
                         SMEM_BYTES);

    // Phase 1: gather + transpose h (and a) into fp16 scratch
    dim3 tg(C8, BB);     // 13 x 32
    transpose_kernel<<<tg, 256>>>(inputs, emb, a0, a1, a2, a3);

    // Phase 2: fused score/softmax/aggregate
    dim3 grid(NN / IT, BB);   // 25 x 32 = 800 blocks
    gnn_agg_kernel<<<grid, 256, SMEM_BYTES>>>(inputs, adj, emb, out);
}